// round 3
// baseline (speedup 1.0000x reference)
#include <cuda_runtime.h>
#include <cuda_fp16.h>
#include <cstdint>
#include <cstddef>

// ==================== problem dims ====================
#define K_TOK   8192        // B*S
#define K_HID   4096
#define K_HEADS 64
#define K_DIM   64

// ==================== device scratch (module-load allocation; allowed) ====================
static __device__ __half g_Xh [(size_t)K_TOK * K_HID];
static __device__ __half g_Wqh[(size_t)K_HID * K_HID];
static __device__ __half g_Wkh[(size_t)K_HID * K_HID];
static __device__ __half g_Wvh[(size_t)K_HID * K_HID];
static __device__ __half g_Woh[(size_t)K_HID * K_HID];
static __device__ float  g_Q  [(size_t)K_TOK * K_HID];
static __device__ float  g_K  [(size_t)K_TOK * K_HID];
static __device__ float  g_V  [(size_t)K_TOK * K_HID];
static __device__ __half g_Ah [(size_t)K_TOK * K_HID];

// ==================== PTX helpers (base PTX only — no sm_103a-suffix features!) ====================
__device__ __forceinline__ uint32_t smem_u32(const void* p) {
    uint32_t a;
    asm("{ .reg .u64 t; cvta.to.shared.u64 t, %1; cvt.u32.u64 %0, t; }" : "=r"(a) : "l"(p));
    return a;
}
__device__ __forceinline__ void cp_async16(uint32_t saddr, const void* gptr) {
    asm volatile("cp.async.cg.shared.global [%0], [%1], 16;" :: "r"(saddr), "l"(gptr) : "memory");
}
__device__ __forceinline__ void cp_commit() { asm volatile("cp.async.commit_group;" ::: "memory"); }
__device__ __forceinline__ void cp_wait1()  { asm volatile("cp.async.wait_group 1;"  ::: "memory"); }

__device__ __forceinline__ void ldm_x4(uint32_t& r0, uint32_t& r1, uint32_t& r2, uint32_t& r3,
                                       uint32_t addr) {
    asm volatile("ldmatrix.sync.aligned.m8n8.x4.shared.b16 {%0,%1,%2,%3}, [%4];"
                 : "=r"(r0), "=r"(r1), "=r"(r2), "=r"(r3) : "r"(addr));
}
__device__ __forceinline__ void mma16816(float& c0, float& c1, float& c2, float& c3,
                                         uint32_t a0, uint32_t a1, uint32_t a2, uint32_t a3,
                                         uint32_t b0, uint32_t b1) {
    asm volatile("mma.sync.aligned.m16n8k16.row.col.f32.f16.f16.f32 "
                 "{%0,%1,%2,%3}, {%4,%5,%6,%7}, {%8,%9}, {%0,%1,%2,%3};"
                 : "+f"(c0), "+f"(c1), "+f"(c2), "+f"(c3)
                 : "r"(a0), "r"(a1), "r"(a2), "r"(a3), "r"(b0), "r"(b1));
}

// ==================== conversion kernel ====================
__global__ void cvt_f32_to_f16(const float* __restrict__ in, __half* __restrict__ out, int n4) {
    int i = blockIdx.x * blockDim.x + threadIdx.x;
    int stride = gridDim.x * blockDim.x;
    const float4* in4 = (const float4*)in;
    __half2* out2 = (__half2*)out;
    for (; i < n4; i += stride) {
        float4 v = in4[i];
        out2[2 * i + 0] = __floats2half2_rn(v.x, v.y);
        out2[2 * i + 1] = __floats2half2_rn(v.z, v.w);
    }
}

// ==================== mma.sync GEMM: C[8192,4096] = A[8192,4096] * B[4096,4096]^T ====================
// A, B fp16 row-major (K contiguous) -> mma "row.col". C fp32 row-major.
#define BM 128
#define BN 128
#define BK 32
#define GSTAGES 3
#define NKT (K_HID / BK)            // 128 k-tiles
#define STG_BYTES (BM * BK * 2)     // 8192 (A); B same
#define SA_OFF(s) ((s) * 16384)
#define SB_OFF(s) ((s) * 16384 + 8192)
#define GEMM_SMEM (GSTAGES * 16384) // 49152

// One stage of global->shared: A tile [BM][BK], B tile [BN][BK]; rows = 64B = 4 x 16B chunks,
// chunk swizzle: phys = c ^ ((row>>1)&3)  (conflict-free for cp.async writes and ldmatrix reads)
__device__ __forceinline__ void g2s_stage(uint32_t smem_base, int s, int kt,
                                          const __half* __restrict__ A, const __half* __restrict__ B,
                                          int mBase, int nBase, int tid) {
    const __half* Ab = A + (size_t)mBase * K_HID + kt * BK;
    const __half* Bb = B + (size_t)nBase * K_HID + kt * BK;
    #pragma unroll
    for (int p = 0; p < 2; p++) {
        int idx = tid + p * 256;
        int r = idx >> 2, c = idx & 3;
        uint32_t dst = smem_base + SA_OFF(s) + r * 64 + (((c ^ ((r >> 1) & 3))) << 4);
        cp_async16(dst, Ab + (size_t)r * K_HID + c * 8);
    }
    #pragma unroll
    for (int p = 0; p < 2; p++) {
        int idx = tid + p * 256;
        int r = idx >> 2, c = idx & 3;
        uint32_t dst = smem_base + SB_OFF(s) + r * 64 + (((c ^ ((r >> 1) & 3))) << 4);
        cp_async16(dst, Bb + (size_t)r * K_HID + c * 8);
    }
    cp_commit();
}

__global__ void __launch_bounds__(256, 2) gemm_f16_mma_kernel(
    const __half* __restrict__ A, const __half* __restrict__ B, float* __restrict__ C)
{
    extern __shared__ __align__(128) char smem[];
    uint32_t sb = smem_u32(smem);
    int tid = threadIdx.x;
    int lane = tid & 31, wid = tid >> 5;
    int wm = wid >> 2, wn = wid & 3;          // 2 x 4 warp grid; warp tile 64x32
    int mBase = blockIdx.y * BM, nBase = blockIdx.x * BN;

    float acc[4][4][4];                        // [tm][tn][c0..c3]
    #pragma unroll
    for (int i = 0; i < 4; i++)
        #pragma unroll
        for (int j = 0; j < 4; j++)
            #pragma unroll
            for (int q = 0; q < 4; q++) acc[i][j][q] = 0.f;

    // per-lane ldmatrix address components
    int aRow = wm * 64 + (lane & 15);          // + tm*16 (tm*16 doesn't affect swizzle: (16m>>1)&3==0)
    int aSw  = ((lane & 15) >> 1) & 3;
    int aCHi = lane >> 4;                      // k-chunk low select within k16
    int bRowL = ((lane >> 4) << 3) + (lane & 7);   // local n row (0..15 pattern)
    int bRow = wn * 32 + bRowL;                // + tp*16
    int bSw  = (bRowL >> 1) & 3;               // wn*32, tp*16 are multiples of 8 -> no swizzle effect
    int bCLo = (lane >> 3) & 1;

    // prologue: stages 0,1
    g2s_stage(sb, 0, 0, A, B, mBase, nBase, tid);
    g2s_stage(sb, 1, 1, A, B, mBase, nBase, tid);

    for (int kt = 0; kt < NKT; kt++) {
        cp_wait1();            // stage kt's copies complete (<=1 group pending)
        __syncthreads();       // all threads' copies visible; prev iter's reads done
        if (kt + 2 < NKT) {
            g2s_stage(sb, (kt + 2) % GSTAGES, kt + 2, A, B, mBase, nBase, tid);
        } else {
            cp_commit();       // empty group keeps accounting consistent
        }
        int s = kt % GSTAGES;
        uint32_t sA = sb + SA_OFF(s), sB = sb + SB_OFF(s);

        #pragma unroll
        for (int kh = 0; kh < 2; kh++) {
            uint32_t af[4][4];
            #pragma unroll
            for (int tm = 0; tm < 4; tm++) {
                uint32_t addr = sA + (aRow + tm * 16) * 64 + ((((kh << 1) | aCHi) ^ aSw) << 4);
                ldm_x4(af[tm][0], af[tm][1], af[tm][2], af[tm][3], addr);
            }
            uint32_t bf[2][4];
            #pragma unroll
            for (int tp = 0; tp < 2; tp++) {
                uint32_t addr = sB + (bRow + tp * 16) * 64 + ((((kh << 1) | bCLo) ^ bSw) << 4);
                ldm_x4(bf[tp][0], bf[tp][1], bf[tp][2], bf[tp][3], addr);
            }
            #pragma unroll
            for (int tm = 0; tm < 4; tm++)
                #pragma unroll
                for (int tn = 0; tn < 4; tn++) {
                    uint32_t b0 = bf[tn >> 1][(tn & 1) * 2 + 0];
                    uint32_t b1 = bf[tn >> 1][(tn & 1) * 2 + 1];
                    mma16816(acc[tm][tn][0], acc[tm][tn][1], acc[tm][tn][2], acc[tm][tn][3],
                             af[tm][0], af[tm][1], af[tm][2], af[tm][3], b0, b1);
                }
        }
    }

    // epilogue: c0,c1 -> (row = base + lane/4, col = 2*(lane%4)); c2,c3 -> row+8
    #pragma unroll
    for (int tm = 0; tm < 4; tm++) {
        int m0 = mBase + wm * 64 + tm * 16 + (lane >> 2);
        float* r0 = C + (size_t)m0 * K_HID + nBase + wn * 32 + 2 * (lane & 3);
        float* r1 = r0 + (size_t)8 * K_HID;
        #pragma unroll
        for (int tn = 0; tn < 4; tn++) {
            *(float2*)(r0 + tn * 8) = make_float2(acc[tm][tn][0], acc[tm][tn][1]);
            *(float2*)(r1 + tn * 8) = make_float2(acc[tm][tn][2], acc[tm][tn][3]);
        }
    }
}

// ==================== per-token cross-head attention (fp32) ====================
// scores[h,g] = sum_d q[h,d]*mq[d]*k[g,d]*mkv[d] / 8 ; softmax over g ; out[h,d] = sum_g w*v[g,d]*mkv[d]
#define ATTN_SMEM (4 * 4096 * 4)   // qT, kT, v, wT

__global__ void __launch_bounds__(128) attn_kernel(
    const float* __restrict__ Q, const float* __restrict__ Kt, const float* __restrict__ V,
    const float* __restrict__ mu_q, const float* __restrict__ sigma_q,
    const float* __restrict__ mu_kv, const float* __restrict__ sigma_kv,
    const float* __restrict__ eps_q, const float* __restrict__ eps_kv,
    __half* __restrict__ Aout)
{
    __shared__ float smq[64], smkv[64];
    extern __shared__ float sm[];
    float* qT = sm;                 // [d][h]
    float* kT = sm + 4096;          // [d][g]
    float* vv = sm + 8192;          // [g][d]
    float* wT = sm + 12288;         // [g][h]

    int t = blockIdx.x;
    int tid = threadIdx.x;

    if (tid < 64) {
        float mq  = 1.f / (1.f + __expf(-(mu_q[tid]  + eps_q[tid]  * sigma_q[tid])));
        float mkv = 1.f / (1.f + __expf(-(mu_kv[tid] + eps_kv[tid] * sigma_kv[tid])));
        smq[tid]  = mq * 0.125f;    // fold 1/sqrt(64)
        smkv[tid] = mkv;
    }
    __syncthreads();

    const float4* Qr = (const float4*)(Q  + (size_t)t * K_HID);
    const float4* Kr = (const float4*)(Kt + (size_t)t * K_HID);
    const float4* Vr = (const float4*)(V  + (size_t)t * K_HID);
    for (int i4 = tid; i4 < 1024; i4 += 128) {
        int i = i4 * 4;
        int h = i >> 6, d = i & 63;           // 4 consecutive d, same h
        float4 q4 = Qr[i4], k4 = Kr[i4], v4 = Vr[i4];
        qT[(d + 0) * 64 + h] = q4.x * smq[d + 0];
        qT[(d + 1) * 64 + h] = q4.y * smq[d + 1];
        qT[(d + 2) * 64 + h] = q4.z * smq[d + 2];
        qT[(d + 3) * 64 + h] = q4.w * smq[d + 3];
        kT[(d + 0) * 64 + h] = k4.x * smkv[d + 0];
        kT[(d + 1) * 64 + h] = k4.y * smkv[d + 1];
        kT[(d + 2) * 64 + h] = k4.z * smkv[d + 2];
        kT[(d + 3) * 64 + h] = k4.w * smkv[d + 3];
        float4 vm = make_float4(v4.x * smkv[d + 0], v4.y * smkv[d + 1],
                                v4.z * smkv[d + 2], v4.w * smkv[d + 3]);
        *(float4*)(vv + i) = vm;
    }
    __syncthreads();

    int hq = tid >> 3, gq = tid & 7;
    int hb = hq * 4, gb = gq * 8;

    float acc[4][8];
    #pragma unroll
    for (int i = 0; i < 4; i++)
        #pragma unroll
        for (int j = 0; j < 8; j++) acc[i][j] = 0.f;

    #pragma unroll 4
    for (int d = 0; d < 64; d++) {
        float4 q4 = *(const float4*)(qT + d * 64 + hb);
        float4 ka = *(const float4*)(kT + d * 64 + gb);
        float4 kb = *(const float4*)(kT + d * 64 + gb + 4);
        float qs[4] = {q4.x, q4.y, q4.z, q4.w};
        float ks[8] = {ka.x, ka.y, ka.z, ka.w, kb.x, kb.y, kb.z, kb.w};
        #pragma unroll
        for (int i = 0; i < 4; i++)
            #pragma unroll
            for (int j = 0; j < 8; j++) acc[i][j] = fmaf(qs[i], ks[j], acc[i][j]);
    }

    // softmax over g: each row h is split across 8 lanes (bits 0..2 of tid) x 8 regs
    #pragma unroll
    for (int i = 0; i < 4; i++) {
        float m = acc[i][0];
        #pragma unroll
        for (int j = 1; j < 8; j++) m = fmaxf(m, acc[i][j]);
        m = fmaxf(m, __shfl_xor_sync(0xffffffffu, m, 1));
        m = fmaxf(m, __shfl_xor_sync(0xffffffffu, m, 2));
        m = fmaxf(m, __shfl_xor_sync(0xffffffffu, m, 4));
        float e[8], s = 0.f;
        #pragma unroll
        for (int j = 0; j < 8; j++) { e[j] = __expf(acc[i][j] - m); s += e[j]; }
        s += __shfl_xor_sync(0xffffffffu, s, 1);
        s += __shfl_xor_sync(0xffffffffu, s, 2);
        s += __shfl_xor_sync(0xffffffffu, s, 4);
        float inv = 1.f / s;
        #pragma unroll
        for (int j = 0; j < 8; j++) wT[(gb + j) * 64 + hb + i] = e[j] * inv;
    }
    __syncthreads();

    // out[h, d] = sum_g w[h,g] * v[g,d] ; this thread's d-block = gb
    #pragma unroll
    for (int i = 0; i < 4; i++)
        #pragma unroll
        for (int j = 0; j < 8; j++) acc[i][j] = 0.f;

    #pragma unroll 4
    for (int g = 0; g < 64; g++) {
        float4 w4 = *(const float4*)(wT + g * 64 + hb);
        float4 va = *(const float4*)(vv + g * 64 + gb);
        float4 vb = *(const float4*)(vv + g * 64 + gb + 4);
        float ws[4] = {w4.x, w4.y, w4.z, w4.w};
        float vs[8] = {va.x, va.y, va.z, va.w, vb.x, vb.y, vb.z, vb.w};
        #pragma unroll
        for (int i = 0; i < 4; i++)
            #pragma unroll
            for (int j = 0; j < 8; j++) acc[i][j] = fmaf(ws[i], vs[j], acc[i][j]);
    }

    __half* Ar = Aout + (size_t)t * K_HID;
    #pragma unroll
    for (int i = 0; i < 4; i++) {
        int h = hb + i;
        #pragma unroll
        for (int j = 0; j < 8; j += 2)
            *(__half2*)(Ar + h * 64 + gb + j) = __floats2half2_rn(acc[i][j], acc[i][j + 1]);
    }
}

// ==================== launch ====================
extern "C" void kernel_launch(void* const* d_in, const int* in_sizes, int n_in,
                              void* d_out, int out_size) {
    (void)in_sizes; (void)n_in; (void)out_size;
    const float* X        = (const float*)d_in[0];
    const float* Wq       = (const float*)d_in[1];
    const float* Wk       = (const float*)d_in[2];
    const float* Wv       = (const float*)d_in[3];
    const float* Wo       = (const float*)d_in[4];
    const float* mu_q     = (const float*)d_in[5];
    const float* sigma_q  = (const float*)d_in[6];
    const float* mu_kv    = (const float*)d_in[7];
    const float* sigma_kv = (const float*)d_in[8];
    const float* eps_q    = (const float*)d_in[9];
    const float* eps_kv   = (const float*)d_in[10];

    void *pXh, *pWqh, *pWkh, *pWvh, *pWoh, *pQ, *pK, *pV, *pAh;
    cudaGetSymbolAddress(&pXh,  g_Xh);
    cudaGetSymbolAddress(&pWqh, g_Wqh);
    cudaGetSymbolAddress(&pWkh, g_Wkh);
    cudaGetSymbolAddress(&pWvh, g_Wvh);
    cudaGetSymbolAddress(&pWoh, g_Woh);
    cudaGetSymbolAddress(&pQ,   g_Q);
    cudaGetSymbolAddress(&pK,   g_K);
    cudaGetSymbolAddress(&pV,   g_V);
    cudaGetSymbolAddress(&pAh,  g_Ah);

    cudaFuncSetAttribute(gemm_f16_mma_kernel, cudaFuncAttributeMaxDynamicSharedMemorySize, GEMM_SMEM);
    cudaFuncSetAttribute(attn_kernel,         cudaFuncAttributeMaxDynamicSharedMemorySize, ATTN_SMEM);

    // fp32 -> fp16 conversions
    cvt_f32_to_f16<<<2048, 256>>>(X,  (__half*)pXh,  (K_TOK * K_HID) / 4);
    cvt_f32_to_f16<<<2048, 256>>>(Wq, (__half*)pWqh, (K_HID * K_HID) / 4);
    cvt_f32_to_f16<<<2048, 256>>>(Wk, (__half*)pWkh, (K_HID * K_HID) / 4);
    cvt_f32_to_f16<<<2048, 256>>>(Wv, (__half*)pWvh, (K_HID * K_HID) / 4);
    cvt_f32_to_f16<<<2048, 256>>>(Wo, (__half*)pWoh, (K_HID * K_HID) / 4);

    // Q/K/V projections
    dim3 gg(K_HID / BN, K_TOK / BM);   // (32, 64)
    gemm_f16_mma_kernel<<<gg, 256, GEMM_SMEM>>>((const __half*)pXh, (const __half*)pWqh, (float*)pQ);
    gemm_f16_mma_kernel<<<gg, 256, GEMM_SMEM>>>((const __half*)pXh, (const __half*)pWkh, (float*)pK);
    gemm_f16_mma_kernel<<<gg, 256, GEMM_SMEM>>>((const __half*)pXh, (const __half*)pWvh, (float*)pV);

    // per-token attention across heads
    attn_kernel<<<K_TOK, 128, ATTN_SMEM>>>((const float*)pQ, (const float*)pK, (const float*)pV,
                                           mu_q, sigma_q, mu_kv, sigma_kv, eps_q, eps_kv,
                                           (__half*)pAh);

    // output projection -> d_out (fp32)
    gemm_f16_mma_kernel<<<gg, 256, GEMM_SMEM>>>((const __half*)pAh, (const __half*)pWoh, (float*)d_out);
}

// round 6
// speedup vs baseline: 1.1033x; 1.1033x over previous
#include <cuda_runtime.h>
#include <cuda_fp16.h>
#include <cstdint>
#include <cstddef>

// ==================== problem dims ====================
#define K_TOK   8192        // B*S
#define K_HID   4096
#define K_HEADS 64
#define K_DIM   64

// ==================== device scratch (module-load allocation; allowed) ====================
static __device__ __half g_Xh [(size_t)K_TOK * K_HID];
static __device__ __half g_Wqh[(size_t)K_HID * K_HID];
static __device__ __half g_Wkh[(size_t)K_HID * K_HID];
static __device__ __half g_Wvh[(size_t)K_HID * K_HID];
static __device__ __half g_Woh[(size_t)K_HID * K_HID];
static __device__ __half g_Qh [(size_t)K_TOK * K_HID];
static __device__ __half g_Kh [(size_t)K_TOK * K_HID];
static __device__ __half g_Vh [(size_t)K_TOK * K_HID];
static __device__ __half g_Ah [(size_t)K_TOK * K_HID];

// ==================== PTX helpers (base PTX only — no sm_103a-suffix features!) ====================
__device__ __forceinline__ uint32_t smem_u32(const void* p) {
    uint32_t a;
    asm("{ .reg .u64 t; cvta.to.shared.u64 t, %1; cvt.u32.u64 %0, t; }" : "=r"(a) : "l"(p));
    return a;
}
__device__ __forceinline__ void cp_async16(uint32_t saddr, const void* gptr) {
    asm volatile("cp.async.cg.shared.global [%0], [%1], 16;" :: "r"(saddr), "l"(gptr) : "memory");
}
__device__ __forceinline__ void cp_commit() { asm volatile("cp.async.commit_group;" ::: "memory"); }
__device__ __forceinline__ void cp_wait1()  { asm volatile("cp.async.wait_group 1;"  ::: "memory"); }

__device__ __forceinline__ void ldm_x4(uint32_t& r0, uint32_t& r1, uint32_t& r2, uint32_t& r3,
                                       uint32_t addr) {
    asm volatile("ldmatrix.sync.aligned.m8n8.x4.shared.b16 {%0,%1,%2,%3}, [%4];"
                 : "=r"(r0), "=r"(r1), "=r"(r2), "=r"(r3) : "r"(addr));
}
__device__ __forceinline__ void mma16816(float& c0, float& c1, float& c2, float& c3,
                                         uint32_t a0, uint32_t a1, uint32_t a2, uint32_t a3,
                                         uint32_t b0, uint32_t b1) {
    asm volatile("mma.sync.aligned.m16n8k16.row.col.f32.f16.f16.f32 "
                 "{%0,%1,%2,%3}, {%4,%5,%6,%7}, {%8,%9}, {%0,%1,%2,%3};"
                 : "+f"(c0), "+f"(c1), "+f"(c2), "+f"(c3)
                 : "r"(a0), "r"(a1), "r"(a2), "r"(a3), "r"(b0), "r"(b1));
}

// ==================== conversion kernel ====================
__global__ void cvt_f32_to_f16(const float* __restrict__ in, __half* __restrict__ out, int n4) {
    int i = blockIdx.x * blockDim.x + threadIdx.x;
    int stride = gridDim.x * blockDim.x;
    const float4* in4 = (const float4*)in;
    __half2* out2 = (__half2*)out;
    for (; i < n4; i += stride) {
        float4 v = in4[i];
        out2[2 * i + 0] = __floats2half2_rn(v.x, v.y);
        out2[2 * i + 1] = __floats2half2_rn(v.z, v.w);
    }
}

// ==================== mma.sync GEMM: C[8192,4096] = A[8192,4096] * B[4096,4096]^T ====================
// A, B fp16 row-major (K contiguous) -> mma "row.col". OutT = __half or float, row-major.
// CTA tile 128x128x64, 128 threads, 2x2 warp grid, warp tile 64x64. 3-stage cp.async pipeline.
// SMEM rows are 128 B (BK=64 halfs); swizzle: 16B-chunk c -> c ^ (row & 7)  (== SW128).
#define BM 128
#define BN 128
#define BK 64
#define GSTAGES 3
#define NKT (K_HID / BK)             // 64 k-tiles
#define STG_STRIDE 32768             // A tile 16 KB + B tile 16 KB
#define SA_OFF(s) ((s) * STG_STRIDE)
#define SB_OFF(s) ((s) * STG_STRIDE + 16384)
#define GEMM_SMEM (GSTAGES * STG_STRIDE)   // 98304

__device__ __forceinline__ void g2s_stage(uint32_t smem_base, int s, int kt,
                                          const __half* __restrict__ A, const __half* __restrict__ B,
                                          int mBase, int nBase, int tid) {
    const __half* Ab = A + (size_t)mBase * K_HID + kt * BK;
    const __half* Bb = B + (size_t)nBase * K_HID + kt * BK;
    #pragma unroll
    for (int p = 0; p < 8; p++) {           // 1024 16B-chunks, 128 threads
        int idx = tid + p * 128;
        int r = idx >> 3, c = idx & 7;
        uint32_t dst = smem_base + SA_OFF(s) + r * 128 + ((c ^ (r & 7)) << 4);
        cp_async16(dst, Ab + (size_t)r * K_HID + c * 8);
    }
    #pragma unroll
    for (int p = 0; p < 8; p++) {
        int idx = tid + p * 128;
        int r = idx >> 3, c = idx & 7;
        uint32_t dst = smem_base + SB_OFF(s) + r * 128 + ((c ^ (r & 7)) << 4);
        cp_async16(dst, Bb + (size_t)r * K_HID + c * 8);
    }
    cp_commit();
}

template <typename OutT>
__global__ void __launch_bounds__(128, 2) gemm_f16_mma_kernel(
    const __half* __restrict__ A, const __half* __restrict__ B, OutT* __restrict__ C)
{
    extern __shared__ __align__(128) char smem[];
    uint32_t sb = smem_u32(smem);
    int tid = threadIdx.x;
    int lane = tid & 31, wid = tid >> 5;
    int wm = wid >> 1, wn = wid & 1;          // 2 x 2 warp grid; warp tile 64x64
    int mBase = blockIdx.y * BM, nBase = blockIdx.x * BN;

    float acc[4][8][4];                        // [tm][tn][c0..c3]
    #pragma unroll
    for (int i = 0; i < 4; i++)
        #pragma unroll
        for (int j = 0; j < 8; j++)
            #pragma unroll
            for (int q = 0; q < 4; q++) acc[i][j][q] = 0.f;

    // per-lane ldmatrix address components (row & 7 == lane & 7 for both A and B)
    int aRow = wm * 64 + (lane & 15);
    int aCHi = lane >> 4;                      // k-chunk low bit within a k16 step
    int bRowL = ((lane >> 4) << 3) + (lane & 7);
    int bRow = wn * 64 + bRowL;
    int bCLo = (lane >> 3) & 1;
    int sw = lane & 7;

    // prologue: stages 0,1
    g2s_stage(sb, 0, 0, A, B, mBase, nBase, tid);
    g2s_stage(sb, 1, 1, A, B, mBase, nBase, tid);

    for (int kt = 0; kt < NKT; kt++) {
        cp_wait1();            // stage kt's copies complete (<=1 group pending)
        __syncthreads();       // all threads' copies visible; prev iter's reads done
        if (kt + 2 < NKT) {
            g2s_stage(sb, (kt + 2) % GSTAGES, kt + 2, A, B, mBase, nBase, tid);
        } else {
            cp_commit();       // empty group keeps accounting consistent
        }
        int s = kt % GSTAGES;
        uint32_t sA = sb + SA_OFF(s), sB = sb + SB_OFF(s);

        #pragma unroll
        for (int kh = 0; kh < 4; kh++) {       // 4 x k16 steps cover BK=64
            uint32_t af[4][4];
            #pragma unroll
            for (int tm = 0; tm < 4; tm++) {
                uint32_t addr = sA + (aRow + tm * 16) * 128 + ((((kh << 1) | aCHi) ^ sw) << 4);
                ldm_x4(af[tm][0], af[tm][1], af[tm][2], af[tm][3], addr);
            }
            uint32_t bf[4][4];
            #pragma unroll
            for (int tp = 0; tp < 4; tp++) {
                uint32_t addr = sB + (bRow + tp * 16) * 128 + ((((kh << 1) | bCLo) ^ sw) << 4);
                ldm_x4(bf[tp][0], bf[tp][1], bf[tp][2], bf[tp][3], addr);
            }
            #pragma unroll
            for (int tm = 0; tm < 4; tm++)
                #pragma unroll
                for (int tn = 0; tn < 8; tn++) {
                    uint32_t b0 = bf[tn >> 1][(tn & 1) * 2 + 0];
                    uint32_t b1 = bf[tn >> 1][(tn & 1) * 2 + 1];
                    mma16816(acc[tm][tn][0], acc[tm][tn][1], acc[tm][tn][2], acc[tm][tn][3],
                             af[tm][0], af[tm][1], af[tm][2], af[tm][3], b0, b1);
                }
        }
    }

    // epilogue: c0,c1 -> (row = base + lane/4, col = 2*(lane%4)); c2,c3 -> row+8
    #pragma unroll
    for (int tm = 0; tm < 4; tm++) {
        int m0 = mBase + wm * 64 + tm * 16 + (lane >> 2);
        OutT* r0 = C + (size_t)m0 * K_HID + nBase + wn * 64 + 2 * (lane & 3);
        OutT* r1 = r0 + (size_t)8 * K_HID;
        #pragma unroll
        for (int tn = 0; tn < 8; tn++) {
            if constexpr (sizeof(OutT) == 2) {
                *(__half2*)(r0 + tn * 8) = __floats2half2_rn(acc[tm][tn][0], acc[tm][tn][1]);
                *(__half2*)(r1 + tn * 8) = __floats2half2_rn(acc[tm][tn][2], acc[tm][tn][3]);
            } else {
                *(float2*)(r0 + tn * 8) = make_float2(acc[tm][tn][0], acc[tm][tn][1]);
                *(float2*)(r1 + tn * 8) = make_float2(acc[tm][tn][2], acc[tm][tn][3]);
            }
        }
    }
}

// ==================== per-token cross-head attention (fp32 math, fp16 I/O) ====================
// scores[h,g] = sum_d q[h,d]*mq[d]*k[g,d]*mkv[d] / 8 ; softmax over g ; out[h,d] = sum_g w*v[g,d]*mkv[d]
#define ATTN_SMEM (4 * 4096 * 4)   // qT, kT, v, wT (fp32)

__global__ void __launch_bounds__(128) attn_kernel(
    const __half* __restrict__ Q, const __half* __restrict__ Kt, const __half* __restrict__ V,
    const float* __restrict__ mu_q, const float* __restrict__ sigma_q,
    const float* __restrict__ mu_kv, const float* __restrict__ sigma_kv,
    const float* __restrict__ eps_q, const float* __restrict__ eps_kv,
    __half* __restrict__ Aout)
{
    __shared__ float smq[64], smkv[64];
    extern __shared__ float sm[];
    float* qT = sm;                 // [d][h]
    float* kT = sm + 4096;          // [d][g]
    float* vv = sm + 8192;          // [g][d]
    float* wT = sm + 12288;         // [g][h]

    int t = blockIdx.x;
    int tid = threadIdx.x;

    if (tid < 64) {
        float mq  = 1.f / (1.f + __expf(-(mu_q[tid]  + eps_q[tid]  * sigma_q[tid])));
        float mkv = 1.f / (1.f + __expf(-(mu_kv[tid] + eps_kv[tid] * sigma_kv[tid])));
        smq[tid]  = mq * 0.125f;    // fold 1/sqrt(64)
        smkv[tid] = mkv;
    }
    __syncthreads();

    const uint4* Qr = (const uint4*)(Q  + (size_t)t * K_HID);
    const uint4* Kr = (const uint4*)(Kt + (size_t)t * K_HID);
    const uint4* Vr = (const uint4*)(V  + (size_t)t * K_HID);
    for (int i8 = tid; i8 < 512; i8 += 128) {   // 8 halfs per uint4
        int h = i8 >> 3, db = (i8 & 7) << 3;    // 8 consecutive d, same h(==g)
        uint4 qv = Qr[i8], kv = Kr[i8], v8 = Vr[i8];
        const __half2* q2 = (const __half2*)&qv;
        const __half2* k2 = (const __half2*)&kv;
        const __half2* v2 = (const __half2*)&v8;
        #pragma unroll
        for (int j = 0; j < 4; j++) {
            int d = db + 2 * j;
            float2 fq = __half22float2(q2[j]);
            float2 fk = __half22float2(k2[j]);
            float2 fv = __half22float2(v2[j]);
            qT[(d + 0) * 64 + h] = fq.x * smq[d + 0];
            qT[(d + 1) * 64 + h] = fq.y * smq[d + 1];
            kT[(d + 0) * 64 + h] = fk.x * smkv[d + 0];
            kT[(d + 1) * 64 + h] = fk.y * smkv[d + 1];
            vv[h * 64 + d + 0]   = fv.x * smkv[d + 0];
            vv[h * 64 + d + 1]   = fv.y * smkv[d + 1];
        }
    }
    __syncthreads();

    int hq = tid >> 3, gq = tid & 7;
    int hb = hq * 4, gb = gq * 8;

    float acc[4][8];
    #pragma unroll
    for (int i = 0; i < 4; i++)
        #pragma unroll
        for (int j = 0; j < 8; j++) acc[i][j] = 0.f;

    #pragma unroll 4
    for (int d = 0; d < 64; d++) {
        float4 q4 = *(const float4*)(qT + d * 64 + hb);
        float4 ka = *(const float4*)(kT + d * 64 + gb);
        float4 kb = *(const float4*)(kT + d * 64 + gb + 4);
        float qs[4] = {q4.x, q4.y, q4.z, q4.w};
        float ks[8] = {ka.x, ka.y, ka.z, ka.w, kb.x, kb.y, kb.z, kb.w};
        #pragma unroll
        for (int i = 0; i < 4; i++)
            #pragma unroll
            for (int j = 0; j < 8; j++) acc[i][j] = fmaf(qs[i], ks[j], acc[i][j]);
    }

    // softmax over g: each row h is split across 8 lanes (bits 0..2 of tid) x 8 regs
    #pragma unroll
    for (int i = 0; i < 4; i++) {
        float m = acc[i][0];
        #pragma unroll
        for (int j = 1; j < 8; j++) m = fmaxf(m, acc[i][j]);
        m = fmaxf(m, __shfl_xor_sync(0xffffffffu, m, 1));
        m = fmaxf(m, __shfl_xor_sync(0xffffffffu, m, 2));
        m = fmaxf(m, __shfl_xor_sync(0xffffffffu, m, 4));
        float e[8], s = 0.f;
        #pragma unroll
        for (int j = 0; j < 8; j++) { e[j] = __expf(acc[i][j] - m); s += e[j]; }
        s += __shfl_xor_sync(0xffffffffu, s, 1);
        s += __shfl_xor_sync(0xffffffffu, s, 2);
        s += __shfl_xor_sync(0xffffffffu, s, 4);
        float inv = 1.f / s;
        #pragma unroll
        for (int j = 0; j < 8; j++) wT[(gb + j) * 64 + hb + i] = e[j] * inv;
    }
    __syncthreads();

    // out[h, d] = sum_g w[h,g] * v[g,d] ; this thread's d-block = gb
    #pragma unroll
    for (int i = 0; i < 4; i++)
        #pragma unroll
        for (int j = 0; j < 8; j++) acc[i][j] = 0.f;

    #pragma unroll 4
    for (int g = 0; g < 64; g++) {
        float4 w4 = *(const float4*)(wT + g * 64 + hb);
        float4 va = *(const float4*)(vv + g * 64 + gb);
        float4 vb = *(const float4*)(vv + g * 64 + gb + 4);
        float ws[4] = {w4.x, w4.y, w4.z, w4.w};
        float vs[8] = {va.x, va.y, va.z, va.w, vb.x, vb.y, vb.z, vb.w};
        #pragma unroll
        for (int i = 0; i < 4; i++)
            #pragma unroll
            for (int j = 0; j < 8; j++) acc[i][j] = fmaf(ws[i], vs[j], acc[i][j]);
    }

    __half* Ar = Aout + (size_t)t * K_HID;
    #pragma unroll
    for (int i = 0; i < 4; i++) {
        int h = hb + i;
        #pragma unroll
        for (int j = 0; j < 8; j += 2)
            *(__half2*)(Ar + h * 64 + gb + j) = __floats2half2_rn(acc[i][j], acc[i][j + 1]);
    }
}

// ==================== launch ====================
extern "C" void kernel_launch(void* const* d_in, const int* in_sizes, int n_in,
                              void* d_out, int out_size) {
    (void)in_sizes; (void)n_in; (void)out_size;
    const float* X        = (const float*)d_in[0];
    const float* Wq       = (const float*)d_in[1];
    const float* Wk       = (const float*)d_in[2];
    const float* Wv       = (const float*)d_in[3];
    const float* Wo       = (const float*)d_in[4];
    const float* mu_q     = (const float*)d_in[5];
    const float* sigma_q  = (const float*)d_in[6];
    const float* mu_kv    = (const float*)d_in[7];
    const float* sigma_kv = (const float*)d_in[8];
    const float* eps_q    = (const float*)d_in[9];
    const float* eps_kv   = (const float*)d_in[10];

    void *pXh, *pWqh, *pWkh, *pWvh, *pWoh, *pQ, *pK, *pV, *pAh;
    cudaGetSymbolAddress(&pXh,  g_Xh);
    cudaGetSymbolAddress(&pWqh, g_Wqh);
    cudaGetSymbolAddress(&pWkh, g_Wkh);
    cudaGetSymbolAddress(&pWvh, g_Wvh);
    cudaGetSymbolAddress(&pWoh, g_Woh);
    cudaGetSymbolAddress(&pQ,   g_Qh);
    cudaGetSymbolAddress(&pK,   g_Kh);
    cudaGetSymbolAddress(&pV,   g_Vh);
    cudaGetSymbolAddress(&pAh,  g_Ah);

    cudaFuncSetAttribute(gemm_f16_mma_kernel<__half>, cudaFuncAttributeMaxDynamicSharedMemorySize, GEMM_SMEM);
    cudaFuncSetAttribute(gemm_f16_mma_kernel<float>,  cudaFuncAttributeMaxDynamicSharedMemorySize, GEMM_SMEM);
    cudaFuncSetAttribute(attn_kernel,                 cudaFuncAttributeMaxDynamicSharedMemorySize, ATTN_SMEM);

    // fp32 -> fp16 conversions
    cvt_f32_to_f16<<<2048, 256>>>(X,  (__half*)pXh,  (K_TOK * K_HID) / 4);
    cvt_f32_to_f16<<<2048, 256>>>(Wq, (__half*)pWqh, (K_HID * K_HID) / 4);
    cvt_f32_to_f16<<<2048, 256>>>(Wk, (__half*)pWkh, (K_HID * K_HID) / 4);
    cvt_f32_to_f16<<<2048, 256>>>(Wv, (__half*)pWvh, (K_HID * K_HID) / 4);
    cvt_f32_to_f16<<<2048, 256>>>(Wo, (__half*)pWoh, (K_HID * K_HID) / 4);

    // Q/K/V projections (fp16 outputs)
    dim3 gg(K_HID / BN, K_TOK / BM);   // (32, 64)
    gemm_f16_mma_kernel<__half><<<gg, 128, GEMM_SMEM>>>((const __half*)pXh, (const __half*)pWqh, (__half*)pQ);
    gemm_f16_mma_kernel<__half><<<gg, 128, GEMM_SMEM>>>((const __half*)pXh, (const __half*)pWkh, (__half*)pK);
    gemm_f16_mma_kernel<__half><<<gg, 128, GEMM_SMEM>>>((const __half*)pXh, (const __half*)pWvh, (__half*)pV);

    // per-token attention across heads
    attn_kernel<<<K_TOK, 128, ATTN_SMEM>>>((const __half*)pQ, (const __half*)pK, (const __half*)pV,
                                           mu_q, sigma_q, mu_kv, sigma_kv, eps_q, eps_kv,
                                           (__half*)pAh);

    // output projection -> d_out (fp32)
    gemm_f16_mma_kernel<float><<<gg, 128, GEMM_SMEM>>>((const __half*)pAh, (const __half*)pWoh, (float*)d_out);
}